// round 11
// baseline (speedup 1.0000x reference)
#include <cuda_runtime.h>
#include <cuda_fp16.h>
#include <cstdint>

#define HH   16
#define TT   2048
#define DD   192
#define NOPE 128
#define ROPE 64
#define LORA 512
#define DV   128
// QSCALE * log2(e) folded into Q conversion; softmax uses ex2
#define QS2  0.10411755368f

#define KCN (TT * LORA)
#define KPN (HH * TT * ROPE)

// ---------------------------------------------------------------------------
// Device-global scratch (allocation-free rule). Pure fp16 operands.
// ---------------------------------------------------------------------------
__device__ __half g_kc_hi[TT * LORA];
__device__ __half g_k_hi [HH * TT * DD];
__device__ __half g_vt_hi[HH * DV * TT];
__device__ __half g_wbT_hi [HH * 128 * LORA];
__device__ __half g_wuvT_hi[HH * DV  * LORA];

// ---------------------------------------------------------------------------
// PTX helpers
// ---------------------------------------------------------------------------
__device__ __forceinline__ void mma_f16(float* c, const uint32_t* a, const uint32_t* b) {
    asm volatile(
        "mma.sync.aligned.m16n8k16.row.col.f32.f16.f16.f32 "
        "{%0,%1,%2,%3}, {%4,%5,%6,%7}, {%8,%9}, {%0,%1,%2,%3};"
        : "+f"(c[0]), "+f"(c[1]), "+f"(c[2]), "+f"(c[3])
        : "r"(a[0]), "r"(a[1]), "r"(a[2]), "r"(a[3]), "r"(b[0]), "r"(b[1]));
}
__device__ __forceinline__ void ldm4(uint32_t* r, uint32_t addr) {
    asm volatile("ldmatrix.sync.aligned.m8n8.x4.shared.b16 {%0,%1,%2,%3}, [%4];"
        : "=r"(r[0]), "=r"(r[1]), "=r"(r[2]), "=r"(r[3]) : "r"(addr));
}
__device__ __forceinline__ uint32_t smem_u32(const void* p) {
    uint32_t a;
    asm("{ .reg .u64 t; cvta.to.shared.u64 t, %1; cvt.u32.u64 %0, t; }"
        : "=r"(a) : "l"(p));
    return a;
}
__device__ __forceinline__ void cpa16(uint32_t s, const void* g) {
    asm volatile("cp.async.cg.shared.global [%0], [%1], 16;" :: "r"(s), "l"(g));
}
#define CPA_COMMIT() asm volatile("cp.async.commit_group;" ::: "memory")
#define CPA_WAIT(n)  asm volatile("cp.async.wait_group %0;" :: "n"(n) : "memory")
__device__ __forceinline__ float ex2f(float x) {
    float y;
    asm("ex2.approx.f32 %0, %1;" : "=f"(y) : "f"(x));
    return y;
}

// ---------------------------------------------------------------------------
// split kernels (Q handled inside flash now)
// ---------------------------------------------------------------------------
__global__ void split_kckp(const float* __restrict__ kc,
                           const float* __restrict__ kpe) {
    int i = blockIdx.x * 256 + threadIdx.x;
    if (i < KCN) {
        g_kc_hi[i] = __float2half_rn(kc[i]);
    } else {
        int j = i - KCN;
        int d = j % ROPE, th = j / ROPE, t = th % TT, h = th / TT;
        g_k_hi[(h * TT + t) * DD + NOPE + d] = __float2half_rn(kpe[t * ROPE + d]);
    }
}

__global__ void split_wbT(const float* __restrict__ w) {
    __shared__ float tile[32][33];
    int h = blockIdx.z, nt = blockIdx.y, kt = blockIdx.x;
    int r = threadIdx.x >> 5, c = threadIdx.x & 31;
    #pragma unroll
    for (int rr = r; rr < 32; rr += 8)
        tile[rr][c] = w[(kt * 32 + rr) * (HH * 256) + h * 256 + nt * 32 + c];
    __syncthreads();
    #pragma unroll
    for (int rr = r; rr < 32; rr += 8)
        g_wbT_hi[(h * 128 + nt * 32 + rr) * LORA + kt * 32 + c] =
            __float2half_rn(tile[c][rr]);
}

__global__ void split_wuvT(const float* __restrict__ w) {
    __shared__ float tile[32][33];
    int h = blockIdx.z, vt = blockIdx.y, kt = blockIdx.x;
    int r = threadIdx.x >> 5, c = threadIdx.x & 31;
    #pragma unroll
    for (int rr = r; rr < 32; rr += 8)
        tile[rr][c] = w[(h * LORA + kt * 32 + rr) * DV + vt * 32 + c];
    __syncthreads();
    #pragma unroll
    for (int rr = r; rr < 32; rr += 8)
        g_wuvT_hi[(h * 128 + vt * 32 + rr) * LORA + kt * 32 + c] =
            __float2half_rn(tile[c][rr]);
}

// ---------------------------------------------------------------------------
// prep (merged, 1-pass): grid 512, 256 threads (8 warps, warp tile 16x128),
// 3-stage cp.async pipeline, 2 CTAs/SM.
//   mode 0: k_nope = kc_hi * wbT_hi^T   -> g_k_hi   (stride DD)
//   mode 1: vt     = wuvT_hi * kc_hi^T  -> g_vt_hi  (stride TT)
// ---------------------------------------------------------------------------
#define PSTR 72
#define PCH  (128 * PSTR)
#define PSTG (2 * PCH)
#define PREP_SMEM (3 * PSTG * 2)          // 110592 B

__global__ __launch_bounds__(256, 2) void prep_mma() {
    extern __shared__ __half sp[];
    const uint32_t sb = smem_u32(sp);

    const int tid = threadIdx.x, w = tid >> 5, lane = tid & 31;
    const int grp = lane >> 2, tig = lane & 3;
    const int mode = blockIdx.x >> 8;
    const int idx0 = blockIdx.x & 255;
    const int h = idx0 & 15, tt = idx0 >> 4;
    const int r0 = w * 16 + grp;

    const int arow = (lane & 7) + ((lane >> 3) & 1) * 8;
    const int acol = ((lane >> 4) & 1) * 8;
    const int brow = (lane & 7) + ((lane >> 4) & 1) * 8;
    const int bcol = ((lane >> 3) & 1) * 8;

    const int ttOff = tt * 128 * LORA, hOff = h * 128 * LORA;
    const __half *pA, *pB;
    __half* D1;
    int dstride;
    if (mode == 0) {
        pA = g_kc_hi + ttOff;   pB = g_wbT_hi + hOff;
        D1 = g_k_hi + (h * TT + tt * 128) * DD;   dstride = DD;
    } else {
        pA = g_wuvT_hi + hOff;  pB = g_kc_hi + ttOff;
        D1 = g_vt_hi + h * DV * TT + tt * 128;    dstride = TT;
    }

    const uint32_t aoff = (uint32_t)(((w * 16 + arow) * PSTR + acol) * 2);
    const uint32_t boff = (uint32_t)((brow * PSTR + bcol) * 2);

    auto issue = [&](int c, int s) {
        uint32_t base = sb + (uint32_t)(s * PSTG) * 2;
        #pragma unroll
        for (int it = 0; it < 4; it++) {
            int i2 = tid + it * 256;
            int r = i2 >> 3, c8 = (i2 & 7) * 8;
            uint32_t so = (uint32_t)((r * PSTR + c8) * 2);
            int go = r * LORA + c * 64 + c8;
            cpa16(base + so, pA + go);
            cpa16(base + (uint32_t)(PCH * 2) + so, pB + go);
        }
        CPA_COMMIT();
    };

    float cc[16][4];
    #pragma unroll
    for (int nt = 0; nt < 16; nt++)
        #pragma unroll
        for (int j = 0; j < 4; j++) cc[nt][j] = 0.f;

    issue(0, 0); issue(1, 1);
    #pragma unroll
    for (int c = 0; c < 8; c++) {
        if (c < 7) { CPA_WAIT(1); } else { CPA_WAIT(0); }
        __syncthreads();
        if (c + 2 < 8) issue(c + 2, (c + 2) % 3);

        uint32_t stb = sb + (uint32_t)((c % 3) * PSTG) * 2;
        uint32_t Ab = stb + aoff;
        uint32_t Bb = stb + (uint32_t)(PCH * 2) + boff;
        #pragma unroll
        for (int ks = 0; ks < 4; ks++) {
            uint32_t a[4];
            ldm4(a, Ab + ks * 32);
            #pragma unroll
            for (int ntp = 0; ntp < 8; ntp++) {
                uint32_t b[4];
                ldm4(b, Bb + (uint32_t)(ntp * 16 * PSTR * 2) + ks * 32);
                mma_f16(cc[2 * ntp],     a, b);
                mma_f16(cc[2 * ntp + 1], a, b + 2);
            }
        }
    }

    #pragma unroll
    for (int nt = 0; nt < 16; nt++) {
        int col = nt * 8 + 2 * tig;
        *(__half2*)(D1 + r0 * dstride + col) =
            __floats2half2_rn(cc[nt][0], cc[nt][1]);
        *(__half2*)(D1 + (r0 + 8) * dstride + col) =
            __floats2half2_rn(cc[nt][2], cc[nt][3]);
    }
}

// ---------------------------------------------------------------------------
// Flash: 1 CTA = two q-tiles (15-pr, pr) x one head. Q frags in registers
// (loaded directly from fp32 input with scale*log2e). K,V double-buffered;
// ONE barrier per tile; next K+V issued before S; softmax/PV interleaved
// in column halves to overlap MUFU with HMMA.
// ---------------------------------------------------------------------------
#define QSTR 200
#define VSTR 136
#define FK   (128 * QSTR)
#define FVS  (128 * VSTR)
#define FLASH_SMEM ((2 * FK + 2 * FVS) * 2)   // 172032 B

__global__ __launch_bounds__(256, 1) void flash_mma(const float* __restrict__ qf,
                                                    float* __restrict__ out) {
    extern __shared__ __half sf[];
    const uint32_t sKb = smem_u32(sf);
    const uint32_t sVb = sKb + (uint32_t)(2 * FK) * 2;

    const int tid = threadIdx.x, w = tid >> 5, lane = tid & 31;
    const int grp = lane >> 2, tig = lane & 3;
    const int h = blockIdx.x & 15;
    const int pr = blockIdx.x >> 4;
    const int r0 = w * 16 + grp;

    const int arow = (lane & 7) + ((lane >> 3) & 1) * 8;
    const int acol = ((lane >> 4) & 1) * 8;
    const int brow = (lane & 7) + ((lane >> 4) & 1) * 8;
    const int bcol = ((lane >> 3) & 1) * 8;

    const __half* khb = g_k_hi + h * TT * DD;
    const __half* vhb = g_vt_hi + h * DV * TT;

    const uint32_t qaoff = (uint32_t)(((w * 16 + arow) * QSTR + acol) * 2);
    const uint32_t kboff = (uint32_t)((brow * QSTR + bcol) * 2);
    const uint32_t vboff = (uint32_t)((brow * VSTR + bcol) * 2);

    auto issueK = [&](int kt) {
        uint32_t ks_ = sKb + (uint32_t)((kt & 1) * FK) * 2;
        const __half* kh = khb + kt * 128 * DD;
        #pragma unroll
        for (int it = 0; it < 12; it++) {
            int i2 = tid + it * 256;
            int r = i2 / 24, c8 = (i2 % 24) * 8;
            cpa16(ks_ + (uint32_t)((r * QSTR + c8) * 2), kh + r * DD + c8);
        }
        CPA_COMMIT();
    };
    auto issueV = [&](int kt) {
        uint32_t vs = sVb + (uint32_t)((kt & 1) * FVS) * 2;
        const __half* vh = vhb + kt * 128;
        #pragma unroll
        for (int it = 0; it < 8; it++) {
            int i2 = tid + it * 256;
            int r = i2 >> 4, c8 = (i2 & 15) * 8;
            cpa16(vs + (uint32_t)((r * VSTR + c8) * 2), vh + r * TT + c8);
        }
        CPA_COMMIT();
    };

    for (int seg = 0; seg < 2; seg++) {
        const int qt = seg ? pr : 15 - pr;

        // ---- stage Q: fp32 gmem -> scaled fp16 smem (K stage 0) ----
        __syncthreads();
        {
            const float* qb = qf + ((size_t)qt * 128 * HH + h) * DD;
            #pragma unroll
            for (int it = 0; it < 12; it++) {
                int i2 = tid + it * 256;
                int r = i2 / 24, c8 = (i2 % 24) * 8;
                const float* s = qb + (size_t)r * HH * DD + c8;
                float4 v0 = *(const float4*)(s);
                float4 v1 = *(const float4*)(s + 4);
                __half2 p0 = __floats2half2_rn(v0.x * QS2, v0.y * QS2);
                __half2 p1 = __floats2half2_rn(v0.z * QS2, v0.w * QS2);
                __half2 p2 = __floats2half2_rn(v1.x * QS2, v1.y * QS2);
                __half2 p3 = __floats2half2_rn(v1.z * QS2, v1.w * QS2);
                uint4 u;
                u.x = *(uint32_t*)&p0; u.y = *(uint32_t*)&p1;
                u.z = *(uint32_t*)&p2; u.w = *(uint32_t*)&p3;
                *(uint4*)(sf + r * QSTR + c8) = u;
            }
        }
        __syncthreads();
        uint32_t qa[12][4];
        #pragma unroll
        for (int ks = 0; ks < 12; ks++) ldm4(qa[ks], sKb + qaoff + ks * 32);
        __syncthreads();

        issueK(0);
        issueV(0);

        float oc[16][4];
        #pragma unroll
        for (int nt = 0; nt < 16; nt++)
            #pragma unroll
            for (int j = 0; j < 4; j++) oc[nt][j] = 0.f;
        float ls0 = 0.f, ls1 = 0.f;

        for (int kt = 0; kt <= qt; kt++) {
            CPA_WAIT(0);          // K(kt) and V(kt) both landed
            __syncthreads();
            if (kt < qt) { issueK(kt + 1); issueV(kt + 1); }   // full-tile shadow

            // ---- S = Q K^T (A from registers) ----
            uint32_t Kst = sKb + (uint32_t)((kt & 1) * FK) * 2 + kboff;
            float sc[16][4];
            #pragma unroll
            for (int nt = 0; nt < 16; nt++)
                #pragma unroll
                for (int j = 0; j < 4; j++) sc[nt][j] = 0.f;
            #pragma unroll
            for (int ks = 0; ks < 12; ks++) {
                #pragma unroll
                for (int ntp = 0; ntp < 8; ntp++) {
                    uint32_t b[4];
                    ldm4(b, Kst + (uint32_t)(ntp * 16 * QSTR * 2) + ks * 32);
                    mma_f16(sc[2 * ntp],     qa[ks], b);
                    mma_f16(sc[2 * ntp + 1], qa[ks], b + 2);
                }
            }

            const bool diag = (kt == qt);
            uint32_t Vst = sVb + (uint32_t)((kt & 1) * FVS) * 2 + vboff;

            // ---- halves: exp(half) then PV(half) — MUFU overlaps HMMA ----
            #pragma unroll
            for (int half = 0; half < 2; half++) {
                uint32_t ph[4][4];
                #pragma unroll
                for (int nt2 = 0; nt2 < 8; nt2++) {
                    int nt = half * 8 + nt2;
                    int cb = nt * 8 + 2 * tig;
                    float e0 = ex2f(sc[nt][0]);
                    float e1 = ex2f(sc[nt][1]);
                    float e2 = ex2f(sc[nt][2]);
                    float e3 = ex2f(sc[nt][3]);
                    if (diag) {
                        if (cb     > r0)     e0 = 0.f;
                        if (cb + 1 > r0)     e1 = 0.f;
                        if (cb     > r0 + 8) e2 = 0.f;
                        if (cb + 1 > r0 + 8) e3 = 0.f;
                    }
                    ls0 += e0 + e1;
                    ls1 += e2 + e3;
                    int g = nt2 >> 1, hf = (nt2 & 1) << 1;
                    __half2 h01 = __floats2half2_rn(e0, e1);
                    __half2 h23 = __floats2half2_rn(e2, e3);
                    ph[g][hf]     = *(uint32_t*)&h01;
                    ph[g][hf + 1] = *(uint32_t*)&h23;
                }
                #pragma unroll
                for (int ks = 0; ks < 4; ks++) {
                    int kss = half * 4 + ks;
                    #pragma unroll
                    for (int ntp = 0; ntp < 8; ntp++) {
                        uint32_t b[4];
                        ldm4(b, Vst + (uint32_t)(ntp * 16 * VSTR * 2) + kss * 32);
                        mma_f16(oc[2 * ntp],     ph[ks], b);
                        mma_f16(oc[2 * ntp + 1], ph[ks], b + 2);
                    }
                }
            }
        }

        // ---- epilogue ----
        ls0 += __shfl_xor_sync(0xffffffffu, ls0, 1);
        ls0 += __shfl_xor_sync(0xffffffffu, ls0, 2);
        ls1 += __shfl_xor_sync(0xffffffffu, ls1, 1);
        ls1 += __shfl_xor_sync(0xffffffffu, ls1, 2);
        float inv0 = 1.f / ls0, inv1 = 1.f / ls1;
        float* o0 = out + (size_t)(qt * 128 + r0) * (HH * DV) + h * DV;
        float* o1 = o0 + 8 * (HH * DV);
        #pragma unroll
        for (int nt = 0; nt < 16; nt++) {
            int col = nt * 8 + 2 * tig;
            *(float2*)(o0 + col) = make_float2(oc[nt][0] * inv0, oc[nt][1] * inv0);
            *(float2*)(o1 + col) = make_float2(oc[nt][2] * inv1, oc[nt][3] * inv1);
        }
    }
}

// ---------------------------------------------------------------------------
extern "C" void kernel_launch(void* const* d_in, const int* in_sizes, int n_in,
                              void* d_out, int out_size) {
    const float* q    = (const float*)d_in[0];
    const float* kc   = (const float*)d_in[1];
    const float* kpe  = (const float*)d_in[2];
    const float* wkvb = (const float*)d_in[3];
    const float* wuv  = (const float*)d_in[4];
    float* out = (float*)d_out;
    (void)in_sizes; (void)n_in; (void)out_size;

    cudaFuncSetAttribute(prep_mma,
        cudaFuncAttributeMaxDynamicSharedMemorySize, PREP_SMEM);
    cudaFuncSetAttribute(flash_mma,
        cudaFuncAttributeMaxDynamicSharedMemorySize, FLASH_SMEM);

    split_kckp<<<(KCN + KPN) / 256, 256>>>(kc, kpe);
    split_wbT <<<dim3(16, 4, 16), 256>>>(wkvb);
    split_wuvT<<<dim3(16, 4, 16), 256>>>(wuv);
    prep_mma<<<512, 256, PREP_SMEM>>>();
    flash_mma<<<128, 256, FLASH_SMEM>>>(q, out);
}

// round 12
// speedup vs baseline: 1.4680x; 1.4680x over previous
#include <cuda_runtime.h>
#include <cuda_fp16.h>
#include <cstdint>

#define HH   16
#define TT   2048
#define DD   192
#define NOPE 128
#define ROPE 64
#define LORA 512
#define DV   128
// (1/sqrt(192)) * log2(e) folded into Q conversion; softmax uses ex2.approx
#define QS2  0.10411755368f

#define KCN (TT * LORA)
#define KPN (HH * TT * ROPE)

// ---------------------------------------------------------------------------
// Device-global scratch (allocation-free rule). Pure fp16 operands.
// ---------------------------------------------------------------------------
__device__ __half g_kc_hi[TT * LORA];
__device__ __half g_k_hi [HH * TT * DD];
__device__ __half g_vt_hi[HH * DV * TT];
__device__ __half g_wbT_hi [HH * 128 * LORA];
__device__ __half g_wuvT_hi[HH * DV  * LORA];

// ---------------------------------------------------------------------------
// PTX helpers
// ---------------------------------------------------------------------------
__device__ __forceinline__ void mma_f16(float* c, const uint32_t* a, const uint32_t* b) {
    asm volatile(
        "mma.sync.aligned.m16n8k16.row.col.f32.f16.f16.f32 "
        "{%0,%1,%2,%3}, {%4,%5,%6,%7}, {%8,%9}, {%0,%1,%2,%3};"
        : "+f"(c[0]), "+f"(c[1]), "+f"(c[2]), "+f"(c[3])
        : "r"(a[0]), "r"(a[1]), "r"(a[2]), "r"(a[3]), "r"(b[0]), "r"(b[1]));
}
__device__ __forceinline__ void ldm4(uint32_t* r, uint32_t addr) {
    asm volatile("ldmatrix.sync.aligned.m8n8.x4.shared.b16 {%0,%1,%2,%3}, [%4];"
        : "=r"(r[0]), "=r"(r[1]), "=r"(r[2]), "=r"(r[3]) : "r"(addr));
}
__device__ __forceinline__ uint32_t smem_u32(const void* p) {
    uint32_t a;
    asm("{ .reg .u64 t; cvta.to.shared.u64 t, %1; cvt.u32.u64 %0, t; }"
        : "=r"(a) : "l"(p));
    return a;
}
__device__ __forceinline__ void cpa16(uint32_t s, const void* g) {
    asm volatile("cp.async.cg.shared.global [%0], [%1], 16;" :: "r"(s), "l"(g));
}
#define CPA_COMMIT() asm volatile("cp.async.commit_group;" ::: "memory")
#define CPA_WAIT(n)  asm volatile("cp.async.wait_group %0;" :: "n"(n) : "memory")
__device__ __forceinline__ float ex2f(float x) {
    float y;
    asm("ex2.approx.f32 %0, %1;" : "=f"(y) : "f"(x));
    return y;
}

// ---------------------------------------------------------------------------
// split kernels (Q handled inside flash)
// ---------------------------------------------------------------------------
__global__ void split_kckp(const float* __restrict__ kc,
                           const float* __restrict__ kpe) {
    int i = blockIdx.x * 256 + threadIdx.x;
    if (i < KCN) {
        g_kc_hi[i] = __float2half_rn(kc[i]);
    } else {
        int j = i - KCN;
        int d = j % ROPE, th = j / ROPE, t = th % TT, h = th / TT;
        g_k_hi[(h * TT + t) * DD + NOPE + d] = __float2half_rn(kpe[t * ROPE + d]);
    }
}

// merged weight transposes: z 0..15 -> wbT (h=z), z 16..31 -> wuvT (h=z-16)
__global__ void split_w(const float* __restrict__ wb,
                        const float* __restrict__ wuv) {
    __shared__ float tile[32][33];
    int z = blockIdx.z, nt = blockIdx.y, kt = blockIdx.x;
    int r = threadIdx.x >> 5, c = threadIdx.x & 31;
    if (z < 16) {
        int h = z;
        #pragma unroll
        for (int rr = r; rr < 32; rr += 8)
            tile[rr][c] = wb[(kt * 32 + rr) * (HH * 256) + h * 256 + nt * 32 + c];
        __syncthreads();
        #pragma unroll
        for (int rr = r; rr < 32; rr += 8)
            g_wbT_hi[(h * 128 + nt * 32 + rr) * LORA + kt * 32 + c] =
                __float2half_rn(tile[c][rr]);
    } else {
        int h = z - 16;
        #pragma unroll
        for (int rr = r; rr < 32; rr += 8)
            tile[rr][c] = wuv[(h * LORA + kt * 32 + rr) * DV + nt * 32 + c];
        __syncthreads();
        #pragma unroll
        for (int rr = r; rr < 32; rr += 8)
            g_wuvT_hi[(h * 128 + nt * 32 + rr) * LORA + kt * 32 + c] =
                __float2half_rn(tile[c][rr]);
    }
}

// ---------------------------------------------------------------------------
// prep (merged, 1-pass both modes): grid 512, 512 threads (16 warps, 16x64).
//   mode 0: k_nope = kc_hi * wbT_hi^T   -> g_k_hi   (stride DD)
//   mode 1: vt     = wuvT_hi * kc_hi^T  -> g_vt_hi  (stride TT)
// cp.async 4-stage chunk pipeline (K chunks of 64), one sync per chunk.
// ---------------------------------------------------------------------------
#define PSTR 72
#define PCH  (128 * PSTR)                 // 9216 halfs per array
#define PREP_SMEM (4 * 2 * PCH * 2)       // 147456 B

__global__ __launch_bounds__(512, 1) void prep_mma() {
    extern __shared__ __half sp[];
    const uint32_t sb = smem_u32(sp);

    const int tid = threadIdx.x, w = tid >> 5, lane = tid & 31;
    const int wr = w >> 1, wc = w & 1;
    const int grp = lane >> 2, tig = lane & 3;
    const int mode = blockIdx.x >> 8;
    const int idx0 = blockIdx.x & 255;
    const int h = idx0 & 15, tt = idx0 >> 4;
    const int r0 = wr * 16 + grp;

    const int arow = (lane & 7) + ((lane >> 3) & 1) * 8;
    const int acol = ((lane >> 4) & 1) * 8;
    const int brow = (lane & 7) + ((lane >> 4) & 1) * 8;
    const int bcol = ((lane >> 3) & 1) * 8;

    const int ttOff = tt * 128 * LORA, hOff = h * 128 * LORA;
    const __half *pA, *pB;
    __half* D1;
    int dstride;
    if (mode == 0) {
        pA = g_kc_hi + ttOff;   pB = g_wbT_hi + hOff;
        D1 = g_k_hi + (h * TT + tt * 128) * DD;   dstride = DD;
    } else {
        pA = g_wuvT_hi + hOff;  pB = g_kc_hi + ttOff;
        D1 = g_vt_hi + h * DV * TT + tt * 128;    dstride = TT;
    }

    const uint32_t aoff = (uint32_t)(((wr * 16 + arow) * PSTR + acol) * 2);
    const uint32_t boff = (uint32_t)(((wc * 64 + brow) * PSTR + bcol) * 2);

    auto issue = [&](int c, int s) {
        uint32_t base = sb + (uint32_t)(s * 2 * PCH) * 2;
        #pragma unroll
        for (int it = 0; it < 2; it++) {
            int i2 = tid + it * 512;
            int r = i2 >> 3, c8 = (i2 & 7) * 8;
            uint32_t so = (uint32_t)((r * PSTR + c8) * 2);
            int go = r * LORA + c * 64 + c8;
            cpa16(base + so, pA + go);
            cpa16(base + (uint32_t)(PCH * 2) + so, pB + go);
        }
        CPA_COMMIT();
    };

    float cc[8][4];
    #pragma unroll
    for (int nt = 0; nt < 8; nt++)
        #pragma unroll
        for (int j = 0; j < 4; j++) cc[nt][j] = 0.f;

    issue(0, 0); issue(1, 1); issue(2, 2);
    #pragma unroll
    for (int c = 0; c < 8; c++) {
        if (c < 6)      { CPA_WAIT(2); }
        else if (c == 6){ CPA_WAIT(1); }
        else            { CPA_WAIT(0); }
        __syncthreads();
        if (c + 3 < 8) issue(c + 3, (c + 3) & 3);

        uint32_t stb = sb + (uint32_t)((c & 3) * 2 * PCH) * 2;
        uint32_t Ab = stb + aoff;
        uint32_t Bb = stb + (uint32_t)(PCH * 2) + boff;
        #pragma unroll
        for (int ks = 0; ks < 4; ks++) {
            uint32_t a[4];
            ldm4(a, Ab + ks * 32);
            #pragma unroll
            for (int ntp = 0; ntp < 4; ntp++) {
                uint32_t b[4];
                ldm4(b, Bb + (uint32_t)(ntp * 16 * PSTR * 2) + ks * 32);
                mma_f16(cc[2 * ntp],     a, b);
                mma_f16(cc[2 * ntp + 1], a, b + 2);
            }
        }
    }

    #pragma unroll
    for (int nt = 0; nt < 8; nt++) {
        int col = wc * 64 + nt * 8 + 2 * tig;
        *(__half2*)(D1 + r0 * dstride + col) =
            __floats2half2_rn(cc[nt][0], cc[nt][1]);
        *(__half2*)(D1 + (r0 + 8) * dstride + col) =
            __floats2half2_rn(cc[nt][2], cc[nt][3]);
    }
}

// ---------------------------------------------------------------------------
// Flash (R9 structure): 1 CTA = two q-tiles (15-pr, pr) x one head.
// Q frags in registers (staged from fp32 input with scale*log2e).
// K,V double-buffered; K(kt+1) issued before S, V(kt+1) before PV.
// ---------------------------------------------------------------------------
#define QSTR 200
#define VSTR 136
#define FK   (128 * QSTR)      // 25600 halfs per stage
#define FVS  (128 * VSTR)      // 17408 halfs per stage
#define FLASH_SMEM ((2 * FK + 2 * FVS) * 2)   // 172032 B

__global__ __launch_bounds__(256, 1) void flash_mma(const float* __restrict__ qf,
                                                    float* __restrict__ out) {
    extern __shared__ __half sf[];
    const uint32_t sKb = smem_u32(sf);
    const uint32_t sVb = sKb + (uint32_t)(2 * FK) * 2;

    const int tid = threadIdx.x, w = tid >> 5, lane = tid & 31;
    const int grp = lane >> 2, tig = lane & 3;
    const int h = blockIdx.x & 15;
    const int pr = blockIdx.x >> 4;
    const int r0 = w * 16 + grp;

    const int arow = (lane & 7) + ((lane >> 3) & 1) * 8;
    const int acol = ((lane >> 4) & 1) * 8;
    const int brow = (lane & 7) + ((lane >> 4) & 1) * 8;
    const int bcol = ((lane >> 3) & 1) * 8;

    const __half* khb = g_k_hi + h * TT * DD;
    const __half* vhb = g_vt_hi + h * DV * TT;

    const uint32_t qaoff = (uint32_t)(((w * 16 + arow) * QSTR + acol) * 2);
    const uint32_t kboff = (uint32_t)((brow * QSTR + bcol) * 2);
    const uint32_t vboff = (uint32_t)((brow * VSTR + bcol) * 2);

    auto issueK = [&](int kt) {
        uint32_t ks_ = sKb + (uint32_t)((kt & 1) * FK) * 2;
        const __half* kh = khb + kt * 128 * DD;
        #pragma unroll
        for (int it = 0; it < 12; it++) {
            int i2 = tid + it * 256;
            int r = i2 / 24, c8 = (i2 % 24) * 8;
            cpa16(ks_ + (uint32_t)((r * QSTR + c8) * 2), kh + r * DD + c8);
        }
        CPA_COMMIT();
    };
    auto issueV = [&](int kt) {
        uint32_t vs = sVb + (uint32_t)((kt & 1) * FVS) * 2;
        const __half* vh = vhb + kt * 128;
        #pragma unroll
        for (int it = 0; it < 8; it++) {
            int i2 = tid + it * 256;
            int r = i2 >> 4, c8 = (i2 & 15) * 8;
            cpa16(vs + (uint32_t)((r * VSTR + c8) * 2), vh + r * TT + c8);
        }
        CPA_COMMIT();
    };

    for (int seg = 0; seg < 2; seg++) {
        const int qt = seg ? pr : 15 - pr;

        // ---- stage Q: fp32 gmem -> scaled fp16 (K stage 0), hoist frags ----
        __syncthreads();
        {
            const float* qb = qf + ((size_t)qt * 128 * HH + h) * DD;
            #pragma unroll
            for (int it = 0; it < 12; it++) {
                int i2 = tid + it * 256;
                int r = i2 / 24, c8 = (i2 % 24) * 8;
                const float* s = qb + (size_t)r * HH * DD + c8;
                float4 v0 = *(const float4*)(s);
                float4 v1 = *(const float4*)(s + 4);
                __half2 p0 = __floats2half2_rn(v0.x * QS2, v0.y * QS2);
                __half2 p1 = __floats2half2_rn(v0.z * QS2, v0.w * QS2);
                __half2 p2 = __floats2half2_rn(v1.x * QS2, v1.y * QS2);
                __half2 p3 = __floats2half2_rn(v1.z * QS2, v1.w * QS2);
                uint4 u;
                u.x = *(uint32_t*)&p0; u.y = *(uint32_t*)&p1;
                u.z = *(uint32_t*)&p2; u.w = *(uint32_t*)&p3;
                *(uint4*)(sf + r * QSTR + c8) = u;
            }
        }
        __syncthreads();
        uint32_t qa[12][4];
        #pragma unroll
        for (int ks = 0; ks < 12; ks++) ldm4(qa[ks], sKb + qaoff + ks * 32);
        __syncthreads();

        issueK(0);
        issueV(0);

        float oc[16][4];
        #pragma unroll
        for (int nt = 0; nt < 16; nt++)
            #pragma unroll
            for (int j = 0; j < 4; j++) oc[nt][j] = 0.f;
        float ls0 = 0.f, ls1 = 0.f;

        for (int kt = 0; kt <= qt; kt++) {
            CPA_WAIT(1);          // K(kt) landed (V(kt) may be in flight)
            __syncthreads();
            if (kt < qt) issueK(kt + 1);   // other K stage; overlaps S

            // ---- S = Q K^T (A from registers) ----
            uint32_t Kst = sKb + (uint32_t)((kt & 1) * FK) * 2 + kboff;
            float sc[16][4];
            #pragma unroll
            for (int nt = 0; nt < 16; nt++)
                #pragma unroll
                for (int j = 0; j < 4; j++) sc[nt][j] = 0.f;
            #pragma unroll
            for (int ks = 0; ks < 12; ks++) {
                #pragma unroll
                for (int ntp = 0; ntp < 8; ntp++) {
                    uint32_t b[4];
                    ldm4(b, Kst + (uint32_t)(ntp * 16 * QSTR * 2) + ks * 32);
                    mma_f16(sc[2 * ntp],     qa[ks], b);
                    mma_f16(sc[2 * ntp + 1], qa[ks], b + 2);
                }
            }

            // ---- softmax: p = ex2(s) (log2e pre-folded), registers only ----
            const bool diag = (kt == qt);
            uint32_t ph[8][4];
            #pragma unroll
            for (int nt = 0; nt < 16; nt++) {
                int cb = nt * 8 + 2 * tig;
                float e0 = ex2f(sc[nt][0]);
                float e1 = ex2f(sc[nt][1]);
                float e2 = ex2f(sc[nt][2]);
                float e3 = ex2f(sc[nt][3]);
                if (diag) {
                    if (cb     > r0)     e0 = 0.f;
                    if (cb + 1 > r0)     e1 = 0.f;
                    if (cb     > r0 + 8) e2 = 0.f;
                    if (cb + 1 > r0 + 8) e3 = 0.f;
                }
                ls0 += e0 + e1;
                ls1 += e2 + e3;
                int g = nt >> 1, hf = (nt & 1) << 1;
                __half2 h01 = __floats2half2_rn(e0, e1);
                __half2 h23 = __floats2half2_rn(e2, e3);
                ph[g][hf]     = *(uint32_t*)&h01;
                ph[g][hf + 1] = *(uint32_t*)&h23;
            }

            if (kt < qt) { CPA_WAIT(1); } else { CPA_WAIT(0); }  // V(kt) landed
            __syncthreads();
            if (kt < qt) issueV(kt + 1);   // other V stage; overlaps PV

            // ---- O += P V^T ----
            uint32_t Vst = sVb + (uint32_t)((kt & 1) * FVS) * 2 + vboff;
            #pragma unroll
            for (int ks = 0; ks < 8; ks++) {
                #pragma unroll
                for (int ntp = 0; ntp < 8; ntp++) {
                    uint32_t b[4];
                    ldm4(b, Vst + (uint32_t)(ntp * 16 * VSTR * 2) + ks * 32);
                    mma_f16(oc[2 * ntp],     ph[ks], b);
                    mma_f16(oc[2 * ntp + 1], ph[ks], b + 2);
                }
            }
        }

        // ---- epilogue ----
        ls0 += __shfl_xor_sync(0xffffffffu, ls0, 1);
        ls0 += __shfl_xor_sync(0xffffffffu, ls0, 2);
        ls1 += __shfl_xor_sync(0xffffffffu, ls1, 1);
        ls1 += __shfl_xor_sync(0xffffffffu, ls1, 2);
        float inv0 = 1.f / ls0, inv1 = 1.f / ls1;
        float* o0 = out + (size_t)(qt * 128 + r0) * (HH * DV) + h * DV;
        float* o1 = o0 + 8 * (HH * DV);
        #pragma unroll
        for (int nt = 0; nt < 16; nt++) {
            int col = nt * 8 + 2 * tig;
            *(float2*)(o0 + col) = make_float2(oc[nt][0] * inv0, oc[nt][1] * inv0);
            *(float2*)(o1 + col) = make_float2(oc[nt][2] * inv1, oc[nt][3] * inv1);
        }
    }
}

// ---------------------------------------------------------------------------
extern "C" void kernel_launch(void* const* d_in, const int* in_sizes, int n_in,
                              void* d_out, int out_size) {
    const float* q    = (const float*)d_in[0];
    const float* kc   = (const float*)d_in[1];
    const float* kpe  = (const float*)d_in[2];
    const float* wkvb = (const float*)d_in[3];
    const float* wuv  = (const float*)d_in[4];
    float* out = (float*)d_out;
    (void)in_sizes; (void)n_in; (void)out_size;

    cudaFuncSetAttribute(prep_mma,
        cudaFuncAttributeMaxDynamicSharedMemorySize, PREP_SMEM);
    cudaFuncSetAttribute(flash_mma,
        cudaFuncAttributeMaxDynamicSharedMemorySize, FLASH_SMEM);

    split_kckp<<<(KCN + KPN) / 256, 256>>>(kc, kpe);
    split_w<<<dim3(16, 4, 32), 256>>>(wkvb, wuv);
    prep_mma<<<512, 512, PREP_SMEM>>>();
    flash_mma<<<128, 256, FLASH_SMEM>>>(q, out);
}